// round 17
// baseline (speedup 1.0000x reference)
#include <cuda_runtime.h>
#include <cuda_fp16.h>
#include <cstdint>

#define BOOKS 8
#define NROWS 1024
#define INFEAT 2048
#define OUTF 4096
#define LW 256
#define WORDS 256

// Scratch (device globals; no runtime allocation allowed)
__device__ __half g_x[BOOKS * NROWS * LW];     // fp16(xn)
__device__ __half g_s[BOOKS * NROWS * LW];     // fp16(sn)
__device__ __half g_w[BOOKS * OUTF * LW];      // fp16(weight)
__device__ float g_winv[BOOKS * OUTF];
__device__ float g_cbT[BOOKS * WORDS * LW];    // cb transposed: [b][w][d]

// ===========================================================================
// helpers
// ===========================================================================
__device__ __forceinline__ uint32_t smem_u32(const void* p) {
    uint32_t a;
    asm("{ .reg .u64 t; cvta.to.shared.u64 t, %1; cvt.u32.u64 %0, t; }" : "=r"(a) : "l"(p));
    return a;
}
__device__ __forceinline__ void cp16(uint32_t dst, const void* src) {
    asm volatile("cp.async.cg.shared.global [%0], [%1], 16;" :: "r"(dst), "l"(src));
}
__device__ __forceinline__ void cp_commit() { asm volatile("cp.async.commit_group;"); }
__device__ __forceinline__ void cp_wait1()  { asm volatile("cp.async.wait_group 1;"); }
__device__ __forceinline__ void cp_wait0()  { asm volatile("cp.async.wait_group 0;"); }

__device__ __forceinline__ void ldm4(uint32_t* r, uint32_t addr) {
    asm volatile("ldmatrix.sync.aligned.m8n8.x4.shared.b16 {%0,%1,%2,%3}, [%4];"
                 : "=r"(r[0]), "=r"(r[1]), "=r"(r[2]), "=r"(r[3]) : "r"(addr));
}
__device__ __forceinline__ void mma16816f(float* d, const uint32_t* a, const uint32_t* b) {
    asm volatile(
        "mma.sync.aligned.m16n8k16.row.col.f32.f16.f16.f32 "
        "{%0,%1,%2,%3}, {%4,%5,%6,%7}, {%8,%9}, {%0,%1,%2,%3};"
        : "+f"(d[0]), "+f"(d[1]), "+f"(d[2]), "+f"(d[3])
        : "r"(a[0]), "r"(a[1]), "r"(a[2]), "r"(a[3]), "r"(b[0]), "r"(b[1]));
}

// ---------------------------------------------------------------------------
// prep: blocks [0,4096): winv + fp16 weight (1 warp/row, 8 rows/block).
//       blocks [4096,4608): codebook transpose tile (32x32).
// ---------------------------------------------------------------------------
__global__ void prep_kernel(const float* __restrict__ weight,
                            const float* __restrict__ cb) {
    __shared__ float tile[32][33];
    int t = threadIdx.x;
    if (blockIdx.x < 4096) {
        int row  = blockIdx.x * 8 + (t >> 5);
        int lane = t & 31;
        const float4* w4 = (const float4*)(weight + (size_t)row * LW);
        float ss = 0.f;
        float4 v[2];
#pragma unroll
        for (int j = 0; j < 2; j++) {
            v[j] = w4[lane + 32 * j];
            ss += v[j].x * v[j].x + v[j].y * v[j].y + v[j].z * v[j].z + v[j].w * v[j].w;
        }
#pragma unroll
        for (int o = 16; o > 0; o >>= 1) ss += __shfl_xor_sync(0xffffffffu, ss, o);
        if (lane == 0) g_winv[row] = 1.0f / fmaxf(sqrtf(ss), 1e-12f);
#pragma unroll
        for (int j = 0; j < 2; j++) {
            size_t i2 = (size_t)row * (LW / 2) + (lane + 32 * j) * 2;
            ((__half2*)g_w)[i2]     = __half2(__float2half(v[j].x), __float2half(v[j].y));
            ((__half2*)g_w)[i2 + 1] = __half2(__float2half(v[j].z), __float2half(v[j].w));
        }
    } else {
        int bi = blockIdx.x - 4096;          // 512 tiles: b(8) x d0(8) x w0(8)
        int b  = bi >> 6;
        int d0 = ((bi >> 3) & 7) * 32;
        int w0 = (bi & 7) * 32;
        int tx = t & 31, ty = t >> 5;        // (32, 8)
        const float* src = cb + b * 65536;
        float* dst = g_cbT + b * 65536;
#pragma unroll
        for (int j = ty; j < 32; j += 8)
            tile[j][tx] = src[(d0 + j) * 256 + w0 + tx];
        __syncthreads();
#pragma unroll
        for (int j = ty; j < 32; j += 8)
            dst[(w0 + j) * 256 + d0 + tx] = tile[tx][j];
    }
}

// ---------------------------------------------------------------------------
// bookA: 32 rows/block — halves per-row mlp/cbT L2 traffic.
// xn, softmax(x@mlp)->xc, s=cbT@xc, sn; writes fp16 planes.
// smem: xc_s[32*256] @0 (32KB); x_s[32*256] @8192, ALIASED by s_s[32][257]
// (x dead after logits loop). total 16416 floats = 65664 B.
// ---------------------------------------------------------------------------
__global__ void bookA_kernel(const float* __restrict__ input,
                             const float* __restrict__ mlp,
                             float* __restrict__ out_xc) {
    extern __shared__ float sm[];
    float* xc_s = sm;
    float* x_s  = sm + 8192;
    float* s_s  = sm + 8192;     // alias: x dead before s written
    __shared__ float rinv[32], rmax[32], rsum[32];

    int b = blockIdx.y, n0 = blockIdx.x * 32;
    int t = threadIdx.x, wid = t >> 5, lane = t & 31;

#pragma unroll
    for (int i = 0; i < 32; i++)
        x_s[i * 256 + t] = input[(size_t)(n0 + i) * INFEAT + b * 256 + t];
    __syncthreads();

    for (int i = wid; i < 32; i += 8) {
        float ss = 0.f;
#pragma unroll
        for (int j = 0; j < 8; j++) { float v = x_s[i * 256 + lane + 32 * j]; ss += v * v; }
#pragma unroll
        for (int o = 16; o > 0; o >>= 1) ss += __shfl_xor_sync(0xffffffffu, ss, o);
        if (!lane) rinv[i] = 1.0f / fmaxf(sqrtf(ss), 1e-12f);
    }
    __syncthreads();
#pragma unroll
    for (int i = 0; i < 32; i++) {
        float v = x_s[i * 256 + t] * rinv[i];
        g_x[(size_t)((b << 10) + (n0 + i)) * 256 + t] = __float2half(v);
    }

    // logits[i][t] = sum_d x[i][d] * mlp[b][d][t]
    float acc[32];
#pragma unroll
    for (int i = 0; i < 32; i++) acc[i] = 0.f;
    const float* mp = mlp + b * 65536 + t;
    for (int d = 0; d < 256; d += 4) {
        float m0 = __ldg(mp + (d + 0) * 256);
        float m1 = __ldg(mp + (d + 1) * 256);
        float m2 = __ldg(mp + (d + 2) * 256);
        float m3 = __ldg(mp + (d + 3) * 256);
#pragma unroll
        for (int i = 0; i < 32; i++) {
            float4 xv = *(const float4*)(x_s + i * 256 + d);
            acc[i] += xv.x * m0 + xv.y * m1 + xv.z * m2 + xv.w * m3;
        }
    }
    __syncthreads();
#pragma unroll
    for (int i = 0; i < 32; i++) xc_s[i * 256 + t] = acc[i];
    __syncthreads();

    for (int i = wid; i < 32; i += 8) {
        float m = -3.4e38f;
#pragma unroll
        for (int j = 0; j < 8; j++) m = fmaxf(m, xc_s[i * 256 + lane + 32 * j]);
#pragma unroll
        for (int o = 16; o > 0; o >>= 1) m = fmaxf(m, __shfl_xor_sync(0xffffffffu, m, o));
        float se = 0.f;
#pragma unroll
        for (int j = 0; j < 8; j++) se += expf(xc_s[i * 256 + lane + 32 * j] - m);
#pragma unroll
        for (int o = 16; o > 0; o >>= 1) se += __shfl_xor_sync(0xffffffffu, se, o);
        if (!lane) { rmax[i] = m; rsum[i] = 1.0f / se; }
    }
    __syncthreads();
#pragma unroll
    for (int i = 0; i < 32; i++) {
        float v = expf(acc[i] - rmax[i]) * rsum[i];
        xc_s[i * 256 + t] = v;
        out_xc[(size_t)(n0 + i) * (BOOKS * WORDS) + b * 256 + t] = v;
    }
    __syncthreads();

    // s[i][d] = sum_w cbT[w][d] * xc[i][w]  — thread t owns d=t, coalesced __ldg
    float sacc[32];
#pragma unroll
    for (int i = 0; i < 32; i++) sacc[i] = 0.f;
    const float* cp = g_cbT + b * 65536 + t;
    for (int w = 0; w < 256; w += 4) {
        float c0 = __ldg(cp + (w + 0) * 256);
        float c1 = __ldg(cp + (w + 1) * 256);
        float c2 = __ldg(cp + (w + 2) * 256);
        float c3 = __ldg(cp + (w + 3) * 256);
#pragma unroll
        for (int i = 0; i < 32; i++) {
            float4 a = *(const float4*)(xc_s + i * 256 + w);
            sacc[i] += a.x * c0 + a.y * c1 + a.z * c2 + a.w * c3;
        }
    }
    __syncthreads();                 // x_s reads fully done before alias write
#pragma unroll
    for (int i = 0; i < 32; i++) s_s[i * 257 + t] = sacc[i];
    __syncthreads();

    for (int i = wid; i < 32; i += 8) {
        float ss = 0.f;
#pragma unroll
        for (int j = 0; j < 8; j++) { float v = s_s[i * 257 + lane + 32 * j]; ss += v * v; }
#pragma unroll
        for (int o = 16; o > 0; o >>= 1) ss += __shfl_xor_sync(0xffffffffu, ss, o);
        if (!lane) rinv[i] = 1.0f / fmaxf(sqrtf(ss), 1e-12f);
    }
    __syncthreads();
#pragma unroll
    for (int i = 0; i < 32; i++) {
        float v = s_s[i * 257 + t] * rinv[i];
        g_s[(size_t)((b << 10) + (n0 + i)) * 256 + t] = __float2half(v);
    }
}

// ---------------------------------------------------------------------------
// Dual GEMM: single fp16 MMA per k16 (fp32 accumulate).
// 256 threads / 8 warps, 2 BLOCKS PER SM. Block 64(n) x 128(o), BK=32,
// 3-stage circular cp.async pipeline, warp-specialized:
// warps 0-3 out1(x), 4-7 out2(s); per-group warp grid 1(m) x 4(o),
// warp tile 64x32. Stage: x 5120 + s 5120 + w 10240 = 20480 B, x3.
// ---------------------------------------------------------------------------
#define XS_B 5120
#define W_OFF 10240      // 2*XS_B
#define STAGE_B 20480

__global__ void __launch_bounds__(256, 2)
gemm_mma(const int* __restrict__ label,
         float* __restrict__ out1,
         float* __restrict__ out2) {
    extern __shared__ char smc[];
    __shared__ float winv_s[128];
    uint32_t sb = smem_u32(smc);
    int t = threadIdx.x, wid = t >> 5, lane = t & 31;
    int b = blockIdx.z, n0 = blockIdx.y * 64, o0 = blockIdx.x * 128;

    if (t < 128) winv_s[t] = g_winv[b * OUTF + o0 + t];

    const __half* px = g_x + (size_t)((b << 10) + n0) * 256;
    const __half* ps = g_s + (size_t)((b << 10) + n0) * 256;
    const __half* pw = g_w + ((size_t)b * OUTF + o0) * 256;

    int rowA = t >> 2, seg = t & 3;            // 256 threads -> 64 rows x 4 segs
    uint32_t cpo = (uint32_t)(rowA * 80 + seg * 16);
    int goff = rowA * 256 + seg * 8;

#define LOAD_STAGE(chunk, buf)                                              \
    {                                                                       \
        uint32_t base_ = sb + (uint32_t)(buf) * STAGE_B;                    \
        int g_ = goff + (chunk) * 32;                                       \
        cp16(base_ + cpo,                     px + g_);                     \
        cp16(base_ + XS_B + cpo,              ps + g_);                     \
        cp16(base_ + W_OFF + cpo,             pw + g_);                     \
        cp16(base_ + W_OFF + cpo + 64 * 80,   pw + g_ + 64 * 256);          \
        cp_commit();                                                        \
    }

    int wg = wid >> 2;             // 0: x->out1, 1: s->out2
    int wo = wid & 3;
    int ow0 = wo * 32;
    uint32_t aoff = (uint32_t)wg * XS_B;   // x or s plane

    float acc[4][4][4];
#pragma unroll
    for (int mt = 0; mt < 4; mt++)
#pragma unroll
        for (int ot = 0; ot < 4; ot++)
#pragma unroll
            for (int q = 0; q < 4; q++) acc[mt][ot][q] = 0.f;

    uint32_t a_row = (uint32_t)((lane & 7) + ((lane >> 3) & 1) * 8);
    uint32_t b_row = (uint32_t)(ow0 + (lane & 7) + ((lane >> 4) & 1) * 8);

    LOAD_STAGE(0, 0)
    LOAD_STAGE(1, 1)

    int buf = 0;
    for (int i = 0; i < 8; i++) {
        if (i < 7) cp_wait1(); else cp_wait0();
        __syncthreads();
        if (i + 2 < 8) {
            int nb = buf + 2; if (nb >= 3) nb -= 3;
            LOAD_STAGE(i + 2, nb)
        }
        uint32_t base = sb + (uint32_t)buf * STAGE_B;

#pragma unroll
        for (int kk = 0; kk < 32; kk += 16) {
            uint32_t a_addr = base + aoff + a_row * 80
                            + (uint32_t)((kk + ((lane >> 4) & 1) * 8) * 2);
            uint32_t b_addr = base + W_OFF + b_row * 80
                            + (uint32_t)((kk + ((lane >> 3) & 1) * 8) * 2);

            uint32_t fw[2][4];               // pair p covers ot=2p, 2p+1
#pragma unroll
            for (int p = 0; p < 2; p++)
                ldm4(fw[p], b_addr + (uint32_t)(p * 16 * 80));

#pragma unroll
            for (int mt = 0; mt < 4; mt++) {
                uint32_t fa[4];
                ldm4(fa, a_addr + (uint32_t)(mt * 16 * 80));
#pragma unroll
                for (int ot = 0; ot < 4; ot++)
                    mma16816f(acc[mt][ot], fa, &fw[ot >> 1][(ot & 1) * 2]);
            }
        }
        buf++; if (buf >= 3) buf = 0;
    }

    // ---- epilogue
    float* op = wg ? out2 : out1;
#pragma unroll
    for (int mt = 0; mt < 4; mt++) {
        int r  = n0 + mt * 16 + (lane >> 2);
        int la = label[r], lb = label[r + 8];
        size_t ro  = (size_t)r * (BOOKS * OUTF) + (size_t)b * OUTF;
        size_t ro8 = ro + (size_t)8 * (BOOKS * OUTF);
#pragma unroll
        for (int ot = 0; ot < 4; ot++) {
            int oc = ow0 + ot * 8 + 2 * (lane & 3);
            int o  = o0 + oc;
            float wi0 = winv_s[oc], wi1 = winv_s[oc + 1];
            float* A = acc[mt][ot];
            float v;
            float2 u;
            v = fminf(fmaxf(A[0] * wi0, -1.f), 1.f); if (la == o)     v -= .5f; u.x = 30.f * v;
            v = fminf(fmaxf(A[1] * wi1, -1.f), 1.f); if (la == o + 1) v -= .5f; u.y = 30.f * v;
            *(float2*)(op + ro + o) = u;
            v = fminf(fmaxf(A[2] * wi0, -1.f), 1.f); if (lb == o)     v -= .5f; u.x = 30.f * v;
            v = fminf(fmaxf(A[3] * wi1, -1.f), 1.f); if (lb == o + 1) v -= .5f; u.y = 30.f * v;
            *(float2*)(op + ro8 + o) = u;
        }
    }
}

// ---------------------------------------------------------------------------
extern "C" void kernel_launch(void* const* d_in, const int* in_sizes, int n_in,
                              void* d_out, int out_size) {
    const float* input  = (const float*)d_in[0];
    const int*   label  = (const int*)d_in[1];     // int32 (JAX default x64 off)
    const float* weight = (const float*)d_in[2];
    const float* mlp    = (const float*)d_in[3];
    const float* cb     = (const float*)d_in[4];

    float* out  = (float*)d_out;
    float* out1 = out;                                    // [1024][8][4096]
    float* out2 = out + (size_t)NROWS * BOOKS * OUTF;     // [1024][8][4096]
    float* out3 = out + (size_t)2 * NROWS * BOOKS * OUTF; // [1024][8][256]

    cudaFuncSetAttribute(bookA_kernel, cudaFuncAttributeMaxDynamicSharedMemorySize, 65664);
    cudaFuncSetAttribute(gemm_mma, cudaFuncAttributeMaxDynamicSharedMemorySize, 3 * STAGE_B);

    prep_kernel<<<4096 + 512, 256>>>(weight, cb);
    bookA_kernel<<<dim3(NROWS / 32, BOOKS), 256, 65664>>>(input, mlp, out3);
    gemm_mma<<<dim3(OUTF / 128, NROWS / 64, BOOKS), 256, 3 * STAGE_B>>>(label, out1, out2);
}